// round 9
// baseline (speedup 1.0000x reference)
#include <cuda_runtime.h>
#include <math.h>

typedef unsigned long long u64;

// Device-global accumulators. Last block reads-and-zeros them (atomicExch) so
// every graph replay starts clean. g_done auto-wraps via atomicInc.
__device__ double g_acc[2] = {0.0, 0.0};
__device__ unsigned int g_done = 0;

// ---- packed f32x2 helpers (Blackwell FFMA2 path) ---------------------------
__device__ __forceinline__ u64 pack2(float lo, float hi) {
    u64 r; asm("mov.b64 %0, {%1, %2};" : "=l"(r) : "f"(lo), "f"(hi)); return r;
}
__device__ __forceinline__ void punpack(u64 a, float& x, float& y) {
    asm("mov.b64 {%0, %1}, %2;" : "=f"(x), "=f"(y) : "l"(a));
}
__device__ __forceinline__ u64 padd(u64 a, u64 b) {
    u64 r; asm("add.rn.f32x2 %0, %1, %2;" : "=l"(r) : "l"(a), "l"(b)); return r;
}
__device__ __forceinline__ u64 pmul(u64 a, u64 b) {
    u64 r; asm("mul.rn.f32x2 %0, %1, %2;" : "=l"(r) : "l"(a), "l"(b)); return r;
}
__device__ __forceinline__ u64 pfma(u64 a, u64 b, u64 c) {
    u64 r; asm("fma.rn.f32x2 %0, %1, %2, %3;" : "=l"(r) : "l"(a), "l"(b), "l"(c));
    return r;
}

__inline__ __device__ double warp_reduce(double v) {
    #pragma unroll
    for (int o = 16; o > 0; o >>= 1) v += __shfl_down_sync(0xffffffffu, v, o);
    return v;
}

// ---------------------------------------------------------------------------
// Per-tile SSE body: affine-fit residual via centered moments.
//   SSE = Q - S^2/n - (Sa^2 + Sc^2)/(KZ*V)
// Each thread: 2 adjacent output columns x 8 output rows, packed f32x2 math.
// Dual shared tile: tileB[r][c] = tileA[r][c+1]; every shifted column pair
// {p[c],p[c+1]} is ONE aligned LDS.64 (even c from tileA, odd c from tileB)
// -> zero register-pair marshalling MOVs.
// S/Sc/Sa: sliding window with KZ-deep register history of row stats.
// Q: linear -> accumulated per tile row with trapezoid weights.
// FULL=true: tile fully interior -> weights compile-time, no masks.
// ---------------------------------------------------------------------------
template <int KZ, bool FULL>
__device__ __forceinline__ float body(const float* __restrict__ src, int W,
                                      int outN, int ox0, int oy0,
                                      float* __restrict__ tileA,
                                      float* __restrict__ tileB) {
    constexpr int TY = 8;
    constexpr int SW = 68;                  // padded width (fits kz3 & kz5)
    constexpr int SH = 64 + KZ - 1;

    const int t = threadIdx.y * 32 + threadIdx.x;

    // fill tileA (float4, zero-padded at borders). SW = 68 = 4*17.
    for (int i = t; i < SH * 17; i += 256) {
        int r = i / 17, c4 = (i - r * 17) * 4;
        int gr = oy0 + r, gc = ox0 + c4;
        float4 v;
        if (FULL || (gr < W && gc + 3 < W)) {
            v = *reinterpret_cast<const float4*>(&src[gr * W + gc]);
        } else {
            v = make_float4(0.f, 0.f, 0.f, 0.f);
            if (gr < W) {
                const float* row = &src[gr * W];
                if (gc     < W) v.x = row[gc];
                if (gc + 1 < W) v.y = row[gc + 1];
                if (gc + 2 < W) v.z = row[gc + 2];
                if (gc + 3 < W) v.w = row[gc + 3];
            }
        }
        *reinterpret_cast<float4*>(&tileA[r * SW + c4]) = v;
    }
    __syncthreads();
    // tileB[r][c] = tileA[r][c+1]  (shifted copy -> aligned odd-pair loads)
    for (int i = t; i < SH * 17; i += 256) {
        int r = i / 17, c4 = (i - r * 17) * 4;
        float4 a = *reinterpret_cast<const float4*>(&tileA[r * SW + c4]);
        float nxt = (c4 + 4 < SW) ? tileA[r * SW + c4 + 4] : 0.0f;
        *reinterpret_cast<float4*>(&tileB[r * SW + c4]) =
            make_float4(a.y, a.z, a.w, nxt);
    }
    __syncthreads();

    const float mu = (KZ - 1) * 0.5f;
    float vsum = 0.0f;
    #pragma unroll
    for (int i = 0; i < KZ; i++) vsum += (i - mu) * (i - mu);
    const float inv_n  = 1.0f / (float)(KZ * KZ);
    const float inv_kv = 1.0f / ((float)KZ * vsum);
    const float whi = (float)KZ - mu;

    const u64 NEG1   = pack2(-1.0f, -1.0f);
    const u64 MUp    = pack2(mu, mu);
    const u64 WHIp   = pack2(whi, whi);
    const u64 NINVN  = pack2(-inv_n, -inv_n);
    const u64 NINVKV = pack2(-inv_kv, -inv_kv);
    const u64 ZERO   = pack2(0.0f, 0.0f);

    const int c0 = 2 * threadIdx.x;
    const int ry0 = threadIdx.y * TY;

    u64 maskP = ZERO;
    int nv = TY;
    if (!FULL) {
        maskP = pack2((ox0 + c0 < outN) ? 1.0f : 0.0f,
                      (ox0 + c0 + 1 < outN) ? 1.0f : 0.0f);
        int nvr = outN - oy0 - ry0;
        nv = nvr < 0 ? 0 : (nvr > TY ? TY : nvr);
    }

    const float* Abase = tileA + ry0 * SW + c0;
    const float* Bbase = tileB + ry0 * SW + c0;

    u64 hs[KZ], hc[KZ];
    u64 S = ZERO, Sc = ZERO, Sa = ZERO;
    u64 accP = ZERO;                        // -S^2/n - (Sa^2+Sc^2)/(kV) terms
    u64 accQ = ZERO;                        // weighted q terms

    #pragma unroll
    for (int r = 0; r < TY + KZ - 1; r++) {
        // shifted column pairs, ALL via single aligned LDS.64
        const float* A = Abase + r * SW;
        const float* B = Bbase + r * SW;
        u64 s, cc, q;
        if (KZ == 3) {
            u64 P0 = *reinterpret_cast<const u64*>(A);
            u64 P1 = *reinterpret_cast<const u64*>(B);
            u64 P2 = *reinterpret_cast<const u64*>(A + 2);
            s  = padd(padd(P0, P1), P2);
            cc = pfma(P0, NEG1, P2);
            q  = pmul(P0, P0); q = pfma(P1, P1, q); q = pfma(P2, P2, q);
        } else {
            u64 P0 = *reinterpret_cast<const u64*>(A);
            u64 P1 = *reinterpret_cast<const u64*>(B);
            u64 P2 = *reinterpret_cast<const u64*>(A + 2);
            u64 P3 = *reinterpret_cast<const u64*>(B + 2);
            u64 P4 = *reinterpret_cast<const u64*>(A + 4);
            s = padd(padd(padd(P0, P1), padd(P2, P3)), P4);
            u64 d1 = pfma(P1, NEG1, P3);
            u64 d2 = pfma(P0, NEG1, P4);
            cc = padd(d1, padd(d2, d2));
            q = pmul(P0, P0); q = pfma(P1, P1, q); q = pfma(P2, P2, q);
            q = pfma(P3, P3, q); q = pfma(P4, P4, q);
        }

        // Q is linear in sse: accumulate q with trapezoid weight
        // w_r = #{ valid j : r-KZ+1 <= j <= r, 0 <= j < nv }
        if (FULL) {
            const int lo = (r - (KZ - 1) > 0) ? r - (KZ - 1) : 0;
            const int hi = (r < TY - 1) ? r : TY - 1;
            const float wf = (float)(hi - lo + 1);        // compile-time
            accQ = pfma(q, pack2(wf, wf), accQ);
        } else {
            int lo = r - (KZ - 1); if (lo < 0) lo = 0;
            int hi = r < nv - 1 ? r : nv - 1;
            int w = hi - lo + 1;
            if (w > 0) {
                float wf = (float)w;
                accQ = pfma(q, pack2(wf, wf), accQ);
            }
        }

        const int slot = r % KZ;                          // compile-time
        if (r < KZ) {
            // warmup: direct weighted accumulate (weights are small ints)
            S  = padd(S, s);
            Sc = padd(Sc, cc);
            const int wgt = 2 * r - (KZ - 1);             // 2*(r - mu)
            if (wgt == -4)      Sa = pfma(padd(s, s), NEG1, Sa);
            else if (wgt == -2) Sa = pfma(s, NEG1, Sa);
            else if (wgt == 2)  Sa = padd(Sa, s);
            else if (wgt == 4)  Sa = padd(Sa, padd(s, s));
        } else {
            u64 os = hs[slot];
            S  = padd(S,  pfma(os,       NEG1, s));
            Sc = padd(Sc, pfma(hc[slot], NEG1, cc));
            Sa = pfma(os, MUp, Sa);
            Sa = pfma(s,  WHIp, Sa);
            Sa = pfma(S,  NEG1, Sa);
        }
        hs[slot] = s; hc[slot] = cc;

        if (r >= KZ - 1) {
            int j = r - (KZ - 1);
            if (FULL || j < nv) {
                u64 u = pmul(S, S);
                u64 v = pmul(Sa, Sa);
                v = pfma(Sc, Sc, v);
                u64 e = pmul(u, NINVN);
                e = pfma(v, NINVKV, e);
                accP = padd(accP, e);
            }
        }
    }

    u64 tot = padd(accP, accQ);
    if (!FULL) tot = pmul(tot, maskP);
    float a0, a1;
    punpack(tot, a0, a1);
    return a0 + a1;
}

// ---------------------------------------------------------------------------
// Single fused kernel: both flows in one flat grid + last-block finalize.
// kz=5 blocks scheduled first (heaviest work starts earliest); HW balances.
// ---------------------------------------------------------------------------
__global__ __launch_bounds__(256, 5) void fused_kernel(
    const float* __restrict__ f0, const float* __restrict__ f1,
    int W0, int o0, int gx0, int gy0,
    int W1, int o1, int gx1, int gy1,
    int nb1, unsigned int ntot,
    double n0, double n1, double corr0, double corr1,
    float* __restrict__ out) {
    __shared__ __align__(16) float tileA[68 * 68];
    __shared__ __align__(16) float tileB[68 * 68];
    __shared__ double wsum[8];

    const int bid = blockIdx.x;
    float acc;
    int slot;
    if (bid < nb1) {                      // kz=5 flow first
        int bx = bid % gx1;
        int tmp = bid / gx1;
        int by = tmp % gy1;
        int img = tmp / gy1;
        int ox0 = bx * 64, oy0 = by * 64;
        const float* src = f1 + (size_t)img * W1 * W1;
        if (ox0 + 64 <= o1 && oy0 + 64 <= o1)
            acc = body<5, true >(src, W1, o1, ox0, oy0, tileA, tileB);
        else
            acc = body<5, false>(src, W1, o1, ox0, oy0, tileA, tileB);
        slot = 1;
    } else {
        int lb = bid - nb1;
        int bx = lb % gx0;
        int tmp = lb / gx0;
        int by = tmp % gy0;
        int img = tmp / gy0;
        int ox0 = bx * 64, oy0 = by * 64;
        const float* src = f0 + (size_t)img * W0 * W0;
        if (ox0 + 64 <= o0 && oy0 + 64 <= o0)
            acc = body<3, true >(src, W0, o0, ox0, oy0, tileA, tileB);
        else
            acc = body<3, false>(src, W0, o0, ox0, oy0, tileA, tileB);
        slot = 0;
    }

    // block reduction -> one atomicAdd per block
    double v = warp_reduce((double)acc);
    const int t = threadIdx.y * 32 + threadIdx.x;
    const int lane = t & 31, wid = t >> 5;
    if (lane == 0) wsum[wid] = v;
    __syncthreads();
    if (t == 0) {
        double bv = 0.0;
        #pragma unroll
        for (int i = 0; i < 8; i++) bv += wsum[i];
        atomicAdd(&g_acc[slot], bv);
        __threadfence();
        unsigned int old = atomicInc(&g_done, ntot - 1u);  // wraps to 0 at last
        if (old == ntot - 1u) {
            double a0 = __longlong_as_double(
                atomicExch((unsigned long long*)&g_acc[0], 0ull));
            double a1 = __longlong_as_double(
                atomicExch((unsigned long long*)&g_acc[1], 0ull));
            out[0] = (float)(a0 / n0 + corr0 + a1 / n1 + corr1);
        }
    }
}

// ---------------------------------------------------------------------------
// Host: replicate the reference's KTK construction (fp64 -> fp32 cast) and
// evaluate the coordinate-bias correction analytically.
// ---------------------------------------------------------------------------
static double host_corr(int kz, int W) {
    const int K2 = kz * kz;
    double st = 0.0, st2 = 0.0;
    for (int i = 0; i < kz; i++) { st += i; st2 += (double)i * i; }
    double G00 = kz * st2, G01 = st * st, G02 = kz * st;
    double G11 = kz * st2, G12 = kz * st, G22 = (double)K2;
    double c00 = G11 * G22 - G12 * G12;
    double c01 = G12 * G02 - G01 * G22;
    double c02 = G01 * G12 - G11 * G02;
    double det = G00 * c00 + G01 * c01 + G02 * c02;
    double id = 1.0 / det;
    double Inv[9] = {
        c00 * id, c01 * id, c02 * id,
        c01 * id, (G00 * G22 - G02 * G02) * id, (G02 * G01 - G00 * G12) * id,
        c02 * id, (G02 * G01 - G00 * G12) * id, (G00 * G11 - G01 * G01) * id
    };

    double Kmat[625];  // K2*K2 <= 625
    for (int q = 0; q < K2; q++) {
        double Aq[3] = { (double)(q / kz), (double)(q % kz), 1.0 };
        for (int r = 0; r < K2; r++) {
            double Ar[3] = { (double)(r / kz), (double)(r % kz), 1.0 };
            double p = 0.0;
            for (int i = 0; i < 3; i++)
                for (int j = 0; j < 3; j++)
                    p += Aq[i] * Inv[i * 3 + j] * Ar[j];
            Kmat[q * K2 + r] = p - (q == r ? 1.0 : 0.0);
        }
    }

    double alpha = 0.0, betaC = 0.0, gammaC = 0.0, betaA = 0.0, gammaA = 0.0;
    for (int q = 0; q < K2; q++) {
        for (int r = 0; r < K2; r++) {
            double m64 = 0.0;
            for (int s = 0; s < K2; s++) m64 += Kmat[s * K2 + q] * Kmat[s * K2 + r];
            double m = (double)(float)m64;   // fp32 cast exactly like reference
            double qc = (double)(q % kz), qa = (double)(q / kz);
            double rcv = (double)(r % kz), rav = (double)(r / kz);
            alpha  += m;
            betaC  += m * rcv;
            gammaC += qc * m * rcv;
            betaA  += m * rav;
            gammaA += qa * m * rav;
        }
    }

    double outN = (double)(W - kz + 1);
    double Sw  = outN * (outN - 1.0) * 0.5;
    double Sw2 = (outN - 1.0) * outN * (2.0 * outN - 1.0) / 6.0;
    double corrX = (alpha * Sw2 + 2.0 * betaC * Sw) / outN + gammaC;  // gx
    double corrY = (alpha * Sw2 + 2.0 * betaA * Sw) / outN + gammaA;  // gy
    return corrX + corrY;
}

extern "C" void kernel_launch(void* const* d_in, const int* in_sizes, int n_in,
                              void* d_out, int out_size) {
    const float* f0 = (const float*)d_in[0];
    const float* f1 = (const float*)d_in[1];
    long long s0 = in_sizes[0], s1 = in_sizes[1];
    if (s0 > s1) {  // f0 must be the smaller (kz=3) flow
        const float* tf = f0; f0 = f1; f1 = tf;
        long long ts = s0; s0 = s1; s1 = ts;
    }
    // shape (32, 2, W, W) -> W = sqrt(size / 64)
    int W0 = (int)llround(sqrt((double)s0 / 64.0));
    int W1 = (int)llround(sqrt((double)s1 / 64.0));
    int o0 = W0 - 3 + 1;
    int o1 = W1 - 5 + 1;

    double corr0 = host_corr(3, W0);
    double corr1 = host_corr(5, W1);

    int gx0 = (o0 + 63) / 64, gy0 = (o0 + 63) / 64;
    int gx1 = (o1 + 63) / 64, gy1 = (o1 + 63) / 64;
    int nb0 = gx0 * gy0 * 64;
    int nb1 = gx1 * gy1 * 64;
    unsigned int ntot = (unsigned int)(nb0 + nb1);

    dim3 blk(32, 8);
    fused_kernel<<<ntot, blk>>>(f0, f1,
                                W0, o0, gx0, gy0,
                                W1, o1, gx1, gy1,
                                nb1, ntot,
                                32.0 * o0 * o0, 32.0 * o1 * o1,
                                corr0, corr1,
                                (float*)d_out);
}

// round 10
// speedup vs baseline: 1.7568x; 1.7568x over previous
#include <cuda_runtime.h>
#include <math.h>

typedef unsigned long long u64;

// Device-global accumulators. Last block reads-and-zeros them (atomicExch) so
// every graph replay starts clean. g_done auto-wraps via atomicInc.
__device__ double g_acc[2] = {0.0, 0.0};
__device__ unsigned int g_done = 0;

// ---- packed f32x2 helpers (Blackwell FFMA2 path) ---------------------------
__device__ __forceinline__ u64 pack2(float lo, float hi) {
    u64 r; asm("mov.b64 %0, {%1, %2};" : "=l"(r) : "f"(lo), "f"(hi)); return r;
}
__device__ __forceinline__ void punpack(u64 a, float& x, float& y) {
    asm("mov.b64 {%0, %1}, %2;" : "=f"(x), "=f"(y) : "l"(a));
}
__device__ __forceinline__ u64 padd(u64 a, u64 b) {
    u64 r; asm("add.rn.f32x2 %0, %1, %2;" : "=l"(r) : "l"(a), "l"(b)); return r;
}
__device__ __forceinline__ u64 pmul(u64 a, u64 b) {
    u64 r; asm("mul.rn.f32x2 %0, %1, %2;" : "=l"(r) : "l"(a), "l"(b)); return r;
}
__device__ __forceinline__ u64 pfma(u64 a, u64 b, u64 c) {
    u64 r; asm("fma.rn.f32x2 %0, %1, %2, %3;" : "=l"(r) : "l"(a), "l"(b), "l"(c));
    return r;
}

__inline__ __device__ double warp_reduce(double v) {
    #pragma unroll
    for (int o = 16; o > 0; o >>= 1) v += __shfl_down_sync(0xffffffffu, v, o);
    return v;
}

// ---------------------------------------------------------------------------
// Per-tile SSE body: affine-fit residual via centered moments.
//   SSE = Q - S^2/n - (Sa^2 + Sc^2)/(KZ*V)
// Each thread: 2 adjacent output columns x 8 output rows, packed f32x2 math.
// S/Sc/Sa: sliding window with KZ-deep register history of row stats.
// Q: linear -> accumulated per tile row with trapezoid weights.
// FULL=true: tile fully interior -> weights compile-time, no masks/clamps.
// Single shared tile (LDS bandwidth is the binding constraint; do not add
// shared traffic).
// ---------------------------------------------------------------------------
template <int KZ, bool FULL>
__device__ __forceinline__ float body(const float* __restrict__ src, int W,
                                      int outN, int ox0, int oy0,
                                      float* __restrict__ tile) {
    constexpr int TY = 8;
    constexpr int SW = 68;                  // padded width (fits kz3 & kz5)
    constexpr int SH = 64 + KZ - 1;
    constexpr int NV = KZ + 2;              // window values per thread per row
    constexpr int NL = (NV + 1) / 2;        // float2 loads per row

    const int t = threadIdx.y * 32 + threadIdx.x;

    // float4-vectorized tile fill. SW = 68 = 4*17.
    for (int i = t; i < SH * 17; i += 256) {
        int r = i / 17, c4 = (i - r * 17) * 4;
        int gr = oy0 + r, gc = ox0 + c4;
        float4 v;
        if (FULL || (gr < W && gc + 3 < W)) {
            v = *reinterpret_cast<const float4*>(&src[gr * W + gc]);
        } else {
            v = make_float4(0.f, 0.f, 0.f, 0.f);
            if (gr < W) {
                const float* row = &src[gr * W];
                if (gc     < W) v.x = row[gc];
                if (gc + 1 < W) v.y = row[gc + 1];
                if (gc + 2 < W) v.z = row[gc + 2];
                if (gc + 3 < W) v.w = row[gc + 3];
            }
        }
        *reinterpret_cast<float4*>(&tile[r * SW + c4]) = v;
    }
    __syncthreads();

    const float mu = (KZ - 1) * 0.5f;
    float vsum = 0.0f;
    #pragma unroll
    for (int i = 0; i < KZ; i++) vsum += (i - mu) * (i - mu);
    const float inv_n  = 1.0f / (float)(KZ * KZ);
    const float inv_kv = 1.0f / ((float)KZ * vsum);
    const float whi = (float)KZ - mu;

    const u64 NEG1   = pack2(-1.0f, -1.0f);
    const u64 MUp    = pack2(mu, mu);
    const u64 WHIp   = pack2(whi, whi);
    const u64 NINVN  = pack2(-inv_n, -inv_n);
    const u64 NINVKV = pack2(-inv_kv, -inv_kv);
    const u64 ZERO   = pack2(0.0f, 0.0f);

    const int c0 = 2 * threadIdx.x;
    const int ry0 = threadIdx.y * TY;

    u64 maskP = ZERO;
    int nv = TY;
    if (!FULL) {
        maskP = pack2((ox0 + c0 < outN) ? 1.0f : 0.0f,
                      (ox0 + c0 + 1 < outN) ? 1.0f : 0.0f);
        int nvr = outN - oy0 - ry0;
        nv = nvr < 0 ? 0 : (nvr > TY ? TY : nvr);
    }

    u64 hs[KZ], hc[KZ];
    u64 S = ZERO, Sc = ZERO, Sa = ZERO;
    u64 accP = ZERO;                        // -S^2/n - (Sa^2+Sc^2)/(kV) terms
    u64 accQ = ZERO;                        // weighted q terms

    #pragma unroll
    for (int r = 0; r < TY + KZ - 1; r++) {
        // load window values p[0..NV-1] via aligned LDS.64
        float p[NL * 2];
        #pragma unroll
        for (int j = 0; j < NL; j++) {
            float2 v = *reinterpret_cast<const float2*>(
                &tile[(ry0 + r) * SW + c0 + 2 * j]);
            p[2 * j] = v.x; p[2 * j + 1] = v.y;
        }
        // shifted column pairs P[c] = {p[c], p[c+1]}
        u64 P[KZ];
        #pragma unroll
        for (int c = 0; c < KZ; c++) P[c] = pack2(p[c], p[c + 1]);

        // row stats for BOTH columns per packed op
        u64 s = P[0];
        #pragma unroll
        for (int c = 1; c < KZ; c++) s = padd(s, P[c]);

        u64 cc;
        if (KZ == 3) {
            cc = pfma(P[0], NEG1, P[2]);                 // P2 - P0
        } else {                                          // KZ == 5
            u64 d1 = pfma(P[1], NEG1, P[3]);             // P3 - P1
            u64 d2 = pfma(P[0], NEG1, P[4]);             // P4 - P0
            cc = padd(d1, padd(d2, d2));                 // d1 + 2*d2
        }

        u64 q = pmul(P[0], P[0]);
        #pragma unroll
        for (int c = 1; c < KZ; c++) q = pfma(P[c], P[c], q);

        // Q is linear in sse: accumulate q with trapezoid weight
        // w_r = #{ valid j : r-KZ+1 <= j <= r, 0 <= j < nv }
        if (FULL) {
            const int lo = (r - (KZ - 1) > 0) ? r - (KZ - 1) : 0;
            const int hi = (r < TY - 1) ? r : TY - 1;
            const float wf = (float)(hi - lo + 1);        // compile-time
            accQ = pfma(q, pack2(wf, wf), accQ);
        } else {
            int lo = r - (KZ - 1); if (lo < 0) lo = 0;
            int hi = r < nv - 1 ? r : nv - 1;
            int w = hi - lo + 1;
            if (w > 0) {
                float wf = (float)w;
                accQ = pfma(q, pack2(wf, wf), accQ);
            }
        }

        const int slot = r % KZ;                          // compile-time
        if (r < KZ) {
            // warmup: direct weighted accumulate (weights are small ints)
            S  = padd(S, s);
            Sc = padd(Sc, cc);
            const int wgt = 2 * r - (KZ - 1);             // 2*(r - mu)
            if (wgt == -4)      Sa = pfma(padd(s, s), NEG1, Sa);
            else if (wgt == -2) Sa = pfma(s, NEG1, Sa);
            else if (wgt == 2)  Sa = padd(Sa, s);
            else if (wgt == 4)  Sa = padd(Sa, padd(s, s));
        } else {
            u64 os = hs[slot];
            S  = padd(S,  pfma(os,       NEG1, s));
            Sc = padd(Sc, pfma(hc[slot], NEG1, cc));
            Sa = pfma(os, MUp, Sa);
            Sa = pfma(s,  WHIp, Sa);
            Sa = pfma(S,  NEG1, Sa);
        }
        hs[slot] = s; hc[slot] = cc;

        if (r >= KZ - 1) {
            int j = r - (KZ - 1);
            if (FULL || j < nv) {
                u64 u = pmul(S, S);
                u64 v = pmul(Sa, Sa);
                v = pfma(Sc, Sc, v);
                u64 e = pmul(u, NINVN);
                e = pfma(v, NINVKV, e);
                accP = padd(accP, e);
            }
        }
    }

    u64 tot = padd(accP, accQ);
    if (!FULL) tot = pmul(tot, maskP);
    float a0, a1;
    punpack(tot, a0, a1);
    return a0 + a1;
}

// ---------------------------------------------------------------------------
// Single fused kernel: both flows in one flat grid + last-block finalize.
// kz=5 blocks scheduled first (heaviest work starts earliest); HW balances.
// ---------------------------------------------------------------------------
__global__ __launch_bounds__(256, 5) void fused_kernel(
    const float* __restrict__ f0, const float* __restrict__ f1,
    int W0, int o0, int gx0, int gy0,
    int W1, int o1, int gx1, int gy1,
    int nb1, unsigned int ntot,
    double n0, double n1, double corr0, double corr1,
    float* __restrict__ out) {
    __shared__ __align__(16) float tile[68 * 68];
    __shared__ double wsum[8];

    const int bid = blockIdx.x;
    float acc;
    int slot;
    if (bid < nb1) {                      // kz=5 flow first
        int bx = bid % gx1;
        int tmp = bid / gx1;
        int by = tmp % gy1;
        int img = tmp / gy1;
        int ox0 = bx * 64, oy0 = by * 64;
        const float* src = f1 + (size_t)img * W1 * W1;
        if (ox0 + 64 <= o1 && oy0 + 64 <= o1)
            acc = body<5, true >(src, W1, o1, ox0, oy0, tile);
        else
            acc = body<5, false>(src, W1, o1, ox0, oy0, tile);
        slot = 1;
    } else {
        int lb = bid - nb1;
        int bx = lb % gx0;
        int tmp = lb / gx0;
        int by = tmp % gy0;
        int img = tmp / gy0;
        int ox0 = bx * 64, oy0 = by * 64;
        const float* src = f0 + (size_t)img * W0 * W0;
        if (ox0 + 64 <= o0 && oy0 + 64 <= o0)
            acc = body<3, true >(src, W0, o0, ox0, oy0, tile);
        else
            acc = body<3, false>(src, W0, o0, ox0, oy0, tile);
        slot = 0;
    }

    // block reduction -> one atomicAdd per block
    double v = warp_reduce((double)acc);
    const int t = threadIdx.y * 32 + threadIdx.x;
    const int lane = t & 31, wid = t >> 5;
    if (lane == 0) wsum[wid] = v;
    __syncthreads();
    if (t == 0) {
        double bv = 0.0;
        #pragma unroll
        for (int i = 0; i < 8; i++) bv += wsum[i];
        atomicAdd(&g_acc[slot], bv);
        __threadfence();
        unsigned int old = atomicInc(&g_done, ntot - 1u);  // wraps to 0 at last
        if (old == ntot - 1u) {
            double a0 = __longlong_as_double(
                atomicExch((unsigned long long*)&g_acc[0], 0ull));
            double a1 = __longlong_as_double(
                atomicExch((unsigned long long*)&g_acc[1], 0ull));
            out[0] = (float)(a0 / n0 + corr0 + a1 / n1 + corr1);
        }
    }
}

// ---------------------------------------------------------------------------
// Host: replicate the reference's KTK construction (fp64 -> fp32 cast) and
// evaluate the coordinate-bias correction analytically.
// ---------------------------------------------------------------------------
static double host_corr(int kz, int W) {
    const int K2 = kz * kz;
    double st = 0.0, st2 = 0.0;
    for (int i = 0; i < kz; i++) { st += i; st2 += (double)i * i; }
    double G00 = kz * st2, G01 = st * st, G02 = kz * st;
    double G11 = kz * st2, G12 = kz * st, G22 = (double)K2;
    double c00 = G11 * G22 - G12 * G12;
    double c01 = G12 * G02 - G01 * G22;
    double c02 = G01 * G12 - G11 * G02;
    double det = G00 * c00 + G01 * c01 + G02 * c02;
    double id = 1.0 / det;
    double Inv[9] = {
        c00 * id, c01 * id, c02 * id,
        c01 * id, (G00 * G22 - G02 * G02) * id, (G02 * G01 - G00 * G12) * id,
        c02 * id, (G02 * G01 - G00 * G12) * id, (G00 * G11 - G01 * G01) * id
    };

    double Kmat[625];  // K2*K2 <= 625
    for (int q = 0; q < K2; q++) {
        double Aq[3] = { (double)(q / kz), (double)(q % kz), 1.0 };
        for (int r = 0; r < K2; r++) {
            double Ar[3] = { (double)(r / kz), (double)(r % kz), 1.0 };
            double p = 0.0;
            for (int i = 0; i < 3; i++)
                for (int j = 0; j < 3; j++)
                    p += Aq[i] * Inv[i * 3 + j] * Ar[j];
            Kmat[q * K2 + r] = p - (q == r ? 1.0 : 0.0);
        }
    }

    double alpha = 0.0, betaC = 0.0, gammaC = 0.0, betaA = 0.0, gammaA = 0.0;
    for (int q = 0; q < K2; q++) {
        for (int r = 0; r < K2; r++) {
            double m64 = 0.0;
            for (int s = 0; s < K2; s++) m64 += Kmat[s * K2 + q] * Kmat[s * K2 + r];
            double m = (double)(float)m64;   // fp32 cast exactly like reference
            double qc = (double)(q % kz), qa = (double)(q / kz);
            double rcv = (double)(r % kz), rav = (double)(r / kz);
            alpha  += m;
            betaC  += m * rcv;
            gammaC += qc * m * rcv;
            betaA  += m * rav;
            gammaA += qa * m * rav;
        }
    }

    double outN = (double)(W - kz + 1);
    double Sw  = outN * (outN - 1.0) * 0.5;
    double Sw2 = (outN - 1.0) * outN * (2.0 * outN - 1.0) / 6.0;
    double corrX = (alpha * Sw2 + 2.0 * betaC * Sw) / outN + gammaC;  // gx
    double corrY = (alpha * Sw2 + 2.0 * betaA * Sw) / outN + gammaA;  // gy
    return corrX + corrY;
}

extern "C" void kernel_launch(void* const* d_in, const int* in_sizes, int n_in,
                              void* d_out, int out_size) {
    const float* f0 = (const float*)d_in[0];
    const float* f1 = (const float*)d_in[1];
    long long s0 = in_sizes[0], s1 = in_sizes[1];
    if (s0 > s1) {  // f0 must be the smaller (kz=3) flow
        const float* tf = f0; f0 = f1; f1 = tf;
        long long ts = s0; s0 = s1; s1 = ts;
    }
    // shape (32, 2, W, W) -> W = sqrt(size / 64)
    int W0 = (int)llround(sqrt((double)s0 / 64.0));
    int W1 = (int)llround(sqrt((double)s1 / 64.0));
    int o0 = W0 - 3 + 1;
    int o1 = W1 - 5 + 1;

    double corr0 = host_corr(3, W0);
    double corr1 = host_corr(5, W1);

    int gx0 = (o0 + 63) / 64, gy0 = (o0 + 63) / 64;
    int gx1 = (o1 + 63) / 64, gy1 = (o1 + 63) / 64;
    int nb0 = gx0 * gy0 * 64;
    int nb1 = gx1 * gy1 * 64;
    unsigned int ntot = (unsigned int)(nb0 + nb1);

    dim3 blk(32, 8);
    fused_kernel<<<ntot, blk>>>(f0, f1,
                                W0, o0, gx0, gy0,
                                W1, o1, gx1, gy1,
                                nb1, ntot,
                                32.0 * o0 * o0, 32.0 * o1 * o1,
                                corr0, corr1,
                                (float*)d_out);
}